// round 14
// baseline (speedup 1.0000x reference)
#include <cuda_runtime.h>
#include <cuda.h>
#include <cuda_bf16.h>
#include <cstdint>

// ---------------- problem constants ----------------
#define NROW 8192
#define KDIM 64
#define NAUG 72
#define NTILES 9                 // 72 / 8
#define TILE_M 128
#define KC 32                    // K per chunk (2 x k16 fragments)
#define NTHREADS 256             // 8 warps x 16 rows
#define MTILES (NROW / TILE_M)   // 64
#define NGCHUNK (NROW / KC)      // 256 global k-chunks
#define NSPLIT 7                 // uneven: 4x37 + 3x36 = 256 chunks
#define NPART (MTILES * NSPLIT)  // 448
#define BCH_BYTES (2 * NTILES * 256)     // 4608 bytes per B chunk
#define A_BYTES (TILE_M * 128)           // 16384 (SW128 tile, 128B rows)
#define STAGE_BYTES 21504                // A (16384) + B (4608) rounded to 1024
#define CHUNK_TX (A_BYTES + BCH_BYTES)   // 20992
#define SMEM_BYTES (1024 + 3 * STAGE_BYTES)   // 65536 (incl. alignment slack)

// ---------------- device scratch ----------------
__device__ float g_sq[NROW];
__device__ __align__(16) unsigned char g_yaugB[NGCHUNK * BCH_BYTES];  // 1.18 MB packed bf16
__device__ float g_part[NPART];
__device__ unsigned int g_cnt = 0;

// ---------------- helpers ----------------
__device__ __forceinline__ uint32_t smem_to_u32(const void* p) {
    uint32_t a;
    asm("{ .reg .u64 t; cvta.to.shared.u64 t, %1; cvt.u32.u64 %0, t; }" : "=r"(a) : "l"(p));
    return a;
}
__device__ __forceinline__ uint32_t pack_bf16x2(float lo, float hi) {
    uint32_t r;
    asm("cvt.rn.bf16x2.f32 %0, %1, %2;" : "=r"(r) : "f"(hi), "f"(lo));
    return r;
}
__device__ __forceinline__ void mma_bf16(float* c, const uint32_t* a, uint32_t b0, uint32_t b1) {
    asm volatile(
        "mma.sync.aligned.m16n8k16.row.col.f32.bf16.bf16.f32 "
        "{%0,%1,%2,%3},{%4,%5,%6,%7},{%8,%9},{%0,%1,%2,%3};"
        : "+f"(c[0]), "+f"(c[1]), "+f"(c[2]), "+f"(c[3])
        : "r"(a[0]), "r"(a[1]), "r"(a[2]), "r"(a[3]), "r"(b0), "r"(b1));
}

#define MBARRIER_INIT(mbar, count) \
    asm volatile("mbarrier.init.shared.b64 [%0], %1;" :: "r"((uint32_t)(mbar)), "r"((uint32_t)(count)) : "memory")
#define MBARRIER_EXPECT_TX(mbar, tx) \
    asm volatile("mbarrier.arrive.expect_tx.shared.b64 _, [%0], %1;" :: "r"((uint32_t)(mbar)), "r"((uint32_t)(tx)) : "memory")
#define MBARRIER_WAIT_PARITY(mbar_smem_addr, phase_parity) do { \
    uint32_t _mbar = (uint32_t)(mbar_smem_addr); \
    uint32_t _parity = (uint32_t)(phase_parity); \
    uint32_t _done; \
    asm volatile( \
        "{\n\t.reg .pred p;\n\t" \
        "mbarrier.try_wait.parity.acquire.cta.shared::cta.b64 p, [%1], %2;\n\t" \
        "selp.b32 %0, 1, 0, p;\n\t}" \
        : "=r"(_done) : "r"(_mbar), "r"(_parity) : "memory"); \
    if (!_done) { \
        asm volatile( \
            "{\n\t.reg .pred P1;\n\t" \
            "WAIT_LOOP_%=:\n\t" \
            "mbarrier.try_wait.parity.acquire.cta.shared::cta.b64 P1, [%0], %1, 0x989680;\n\t" \
            "@P1 bra.uni WAIT_DONE_%=;\n\t" \
            "bra.uni WAIT_LOOP_%=;\n\t" \
            "WAIT_DONE_%=:\n\t}" \
            :: "r"(_mbar), "r"(_parity) : "memory"); \
    } \
} while(0)

// byte offset of element (kg, n) inside g_yaugB (fragment-register layout)
__device__ __forceinline__ uint32_t b_offset(int kg, int n) {
    int gc  = kg >> 5;
    int k16 = (kg >> 4) & 1;
    int kl  = kg & 15;
    int nt  = n >> 3;
    int n8  = n & 7;
    int lane = n8 * 4 + ((kl & 7) >> 1);
    return (uint32_t)(((gc * 2 + k16) * NTILES + nt) * 256 + lane * 8
                      + ((kl >> 3) & 1) * 4 + (kl & 1) * 2);
}

// ---------------- prep: sq + fragment-packed bf16 Yaug ----------------
__global__ void prep(const float* __restrict__ Y) {
    int w    = (blockIdx.x * blockDim.x + threadIdx.x) >> 5;
    int lane = threadIdx.x & 31;
    if (w >= NROW) return;
    if (w == 0 && lane == 0) g_cnt = 0;

    const float* yr = Y + (size_t)w * KDIM;
    float v0 = yr[lane], v1 = yr[lane + 32];
    float s = v0 * v0 + v1 * v1;
#pragma unroll
    for (int o = 16; o; o >>= 1) s += __shfl_xor_sync(0xffffffffu, s, o);
    if (lane == 0) g_sq[w] = s;

    *reinterpret_cast<__nv_bfloat16*>(g_yaugB + b_offset(w, lane))      = __float2bfloat16_rn(v0);
    *reinterpret_cast<__nv_bfloat16*>(g_yaugB + b_offset(w, lane + 32)) = __float2bfloat16_rn(v1);
    if (lane < 8) {
        float v = (lane == 0) ? 1.0f : (lane == 1) ? s : 0.0f;
        *reinterpret_cast<__nv_bfloat16*>(g_yaugB + b_offset(w, 64 + lane)) = __float2bfloat16_rn(v);
    }
}

// ---------------- main: TMA bulk loads, 3-stage mbarrier ring ----------------
__global__ __launch_bounds__(NTHREADS, 3)
void spectral_main(const __grid_constant__ CUtensorMap tmapA,
                   const float* __restrict__ Y, float* __restrict__ out) {
    extern __shared__ char smem_raw[];
    char* base = reinterpret_cast<char*>(
        (reinterpret_cast<uintptr_t>(smem_raw) + 1023) & ~(uintptr_t)1023);
    const uint32_t sb = smem_to_u32(base);

    __shared__ __align__(8) uint64_t mbar_store[3];
    __shared__ float red[8];
    __shared__ int flag;
    const uint32_t mb0 = smem_to_u32(mbar_store);

    const int tid  = threadIdx.x;
    const int wid  = tid >> 5;       // 0..7 -> rows wid*16..wid*16+15
    const int lane = tid & 31;
    const int g    = lane >> 2;
    const int tg   = lane & 3;
    const int m0   = blockIdx.x * TILE_M;

    // uneven k-split: by<4 -> 37 chunks, else 36
    const int by    = blockIdx.y;
    const int count = (by < 4) ? 37 : 36;
    const int cs    = (by < 4) ? 37 * by : 148 + 36 * (by - 4);
    const int kbase = cs * KC;

    float acc[NTILES][4];
#pragma unroll
    for (int nt = 0; nt < NTILES; ++nt)
#pragma unroll
        for (int q = 0; q < 4; ++q) acc[nt][q] = 0.0f;

    if (tid == 0) {
#pragma unroll
        for (int s = 0; s < 3; ++s) MBARRIER_INIT(mb0 + s * 8, 1);
    }
    __syncthreads();

    // single-thread issue: one 2D TMA (A, SW128) + one 1D bulk (B) per chunk
    auto issue = [&](int t, int s) {
        const uint32_t mb   = mb0 + (uint32_t)s * 8;
        const uint32_t adst = sb + (uint32_t)s * STAGE_BYTES;
        const uint32_t bdst = adst + A_BYTES;
        const int k0 = kbase + t * KC;
        MBARRIER_EXPECT_TX(mb, CHUNK_TX);
        asm volatile(
            "cp.async.bulk.tensor.2d.shared::cta.global.tile.mbarrier::complete_tx::bytes "
            "[%0], [%1, {%2, %3}], [%4];"
            :: "r"(adst), "l"(&tmapA), "r"(k0), "r"(m0), "r"(mb) : "memory");
        const unsigned char* bsrc = g_yaugB + (size_t)(k0 >> 5) * BCH_BYTES;
        asm volatile(
            "cp.async.bulk.shared::cluster.global.mbarrier::complete_tx::bytes "
            "[%0], [%1], %2, [%3];"
            :: "r"(bdst), "l"(bsrc), "r"((uint32_t)BCH_BYTES), "r"(mb) : "memory");
    };

    if (tid == 0) { issue(0, 0); issue(1, 1); issue(2, 2); }

    int s = 0, ph = 0;
    const int gx = g << 4;           // SW128 xor term: (row&7)<<4, row&7 == g here
    for (int t = 0; t < count; ++t) {
        MBARRIER_WAIT_PARITY(mb0 + s * 8, ph);

        const char* abp = base + (size_t)s * STAGE_BYTES;
        const char* bbp = abp + A_BYTES;
        const int rb = wid * 16;

#pragma unroll
        for (int ks = 0; ks < 2; ++ks) {
            uint32_t a[4];
            {
                const int off0 = (rb + g) * 128 + ks * 64 + tg * 8;
                float2 v0 = *reinterpret_cast<const float2*>(abp + ((off0)        ^ gx));
                float2 v1 = *reinterpret_cast<const float2*>(abp + ((off0 + 1024) ^ gx));
                float2 v2 = *reinterpret_cast<const float2*>(abp + ((off0 + 32)   ^ gx));
                float2 v3 = *reinterpret_cast<const float2*>(abp + ((off0 + 1056) ^ gx));
                a[0] = pack_bf16x2(v0.x, v0.y);
                a[1] = pack_bf16x2(v1.x, v1.y);
                a[2] = pack_bf16x2(v2.x, v2.y);
                a[3] = pack_bf16x2(v3.x, v3.y);
            }
#pragma unroll
            for (int nt = 0; nt < NTILES; ++nt) {
                uint2 b = *reinterpret_cast<const uint2*>(
                    bbp + (ks * NTILES + nt) * 256 + lane * 8);
                mma_bf16(acc[nt], a, b.x, b.y);
            }
        }

        __syncthreads();                       // all threads done reading stage s
        if (t + 3 < count && tid == 0) issue(t + 3, s);
        if (++s == 3) { s = 0; ph ^= 1; }
    }

    // ---- epilogue: contract Z fragments against coefficients ----
    float partial = 0.0f;
#pragma unroll
    for (int half = 0; half < 2; ++half) {
        int i = m0 + wid * 16 + half * 8 + g;
        const float* yr = Y + (size_t)i * KDIM;
        float sacc = 0.0f;
#pragma unroll
        for (int nt = 0; nt < 8; ++nt) {
            int col = nt * 8 + tg * 2;
            sacc = fmaf(yr[col],     acc[nt][half * 2 + 0], sacc);
            sacc = fmaf(yr[col + 1], acc[nt][half * 2 + 1], sacc);
        }
        float e = -2.0f * sacc;
        if (tg == 0) {
            e = fmaf(g_sq[i], acc[8][half * 2 + 0], e);
            e += acc[8][half * 2 + 1];
        }
        partial += e;
    }
#pragma unroll
    for (int o = 16; o; o >>= 1) partial += __shfl_xor_sync(0xffffffffu, partial, o);

    if (lane == 0) red[wid] = partial;
    __syncthreads();

    // ---- last-block deterministic final reduction (448 partials) ----
    if (tid == 0) {
        float c = 0.0f;
#pragma unroll
        for (int j = 0; j < 8; ++j) c += red[j];
        g_part[blockIdx.y * MTILES + blockIdx.x] = c;
        __threadfence();
        unsigned int old = atomicAdd(&g_cnt, 1u);
        flag = (old == NPART - 1) ? 1 : 0;
    }
    __syncthreads();
    if (flag) {
        __threadfence();
        float sv = g_part[tid] + ((tid < NPART - 256) ? g_part[tid + 256] : 0.0f);
#pragma unroll
        for (int o = 16; o; o >>= 1) sv += __shfl_xor_sync(0xffffffffu, sv, o);
        if (lane == 0) red[wid] = sv;
        __syncthreads();
        if (tid == 0) {
            float tot = 0.0f;
#pragma unroll
            for (int j = 0; j < 8; ++j) tot += red[j];
            out[0] = tot * (1.0f / (2.0f * (float)NROW));
            g_cnt = 0;
        }
    }
}

// ---------------- launch ----------------
typedef CUresult (CUDAAPI *tmap_encode_fn)(
    CUtensorMap*, CUtensorMapDataType, cuuint32_t, void*,
    const cuuint64_t*, const cuuint64_t*, const cuuint32_t*, const cuuint32_t*,
    CUtensorMapInterleave, CUtensorMapSwizzle, CUtensorMapL2promotion,
    CUtensorMapFloatOOBfill);

extern "C" void kernel_launch(void* const* d_in, const int* in_sizes, int n_in,
                              void* d_out, int out_size) {
    const float* W;
    const float* Y;
    if (in_sizes[0] == NROW * NROW) {
        W = (const float*)d_in[0];
        Y = (const float*)d_in[1];
    } else {
        Y = (const float*)d_in[0];
        W = (const float*)d_in[1];
    }

    // Build SW128 2D tensor map for W via cudart-resolved driver entry point.
    tmap_encode_fn enc = nullptr;
    cudaDriverEntryPointQueryResult qres;
    cudaGetDriverEntryPointByVersion("cuTensorMapEncodeTiled", (void**)&enc,
                                     12000, cudaEnableDefault, &qres);
    CUtensorMap tmapA;
    {
        cuuint64_t dims[2]    = {NROW, NROW};          // x (contiguous), y
        cuuint64_t strides[1] = {(cuuint64_t)NROW * 4};
        cuuint32_t box[2]     = {32, 128};             // 32 fp32 = 128B x 128 rows
        cuuint32_t es[2]      = {1, 1};
        enc(&tmapA, CU_TENSOR_MAP_DATA_TYPE_FLOAT32, 2, (void*)W,
            dims, strides, box, es,
            CU_TENSOR_MAP_INTERLEAVE_NONE, CU_TENSOR_MAP_SWIZZLE_128B,
            CU_TENSOR_MAP_L2_PROMOTION_L2_128B, CU_TENSOR_MAP_FLOAT_OOB_FILL_NONE);
    }

    cudaFuncSetAttribute(spectral_main, cudaFuncAttributeMaxDynamicSharedMemorySize, SMEM_BYTES);

    prep<<<NROW / 8, 256>>>(Y);
    spectral_main<<<dim3(MTILES, NSPLIT), NTHREADS, SMEM_BYTES>>>(tmapA, Y, (float*)d_out);
}

// round 15
// speedup vs baseline: 1.2385x; 1.2385x over previous
#include <cuda_runtime.h>
#include <cuda.h>
#include <cuda_bf16.h>
#include <cstdint>

// ---------------- problem constants ----------------
#define NROW 8192
#define KDIM 64
#define NAUG 72
#define NTILES 9                 // 72 / 8
#define TILE_M 256
#define KC 32                    // K per chunk (2 x k16 fragments)
#define NTHREADS 256             // 8 warps x 32 rows = 256 rows
#define MTILES (NROW / TILE_M)   // 32
#define NGCHUNK (NROW / KC)      // 256 global k-chunks
#define NSPLIT 9                 // uneven: 4x29 + 5x28 = 256 chunks
#define NPART (MTILES * NSPLIT)  // 288
#define BCH_BYTES (2 * NTILES * 256)     // 4608 bytes per B chunk
#define A_STAGE (TILE_M * 128)           // 32768 (SW128 tile, 128B rows)
#define CHUNK_TX (A_STAGE + BCH_BYTES)   // 37376
#define DYN_BYTES (3 * A_STAGE + 3 * BCH_BYTES + 1024)  // 113152 (incl. align slack)

// ---------------- device scratch ----------------
__device__ float g_sq[NROW];
__device__ __align__(16) unsigned char g_yaugB[NGCHUNK * BCH_BYTES];  // 1.18 MB packed bf16
__device__ float g_part[NPART];
__device__ unsigned int g_cnt = 0;

// ---------------- helpers ----------------
__device__ __forceinline__ uint32_t smem_to_u32(const void* p) {
    uint32_t a;
    asm("{ .reg .u64 t; cvta.to.shared.u64 t, %1; cvt.u32.u64 %0, t; }" : "=r"(a) : "l"(p));
    return a;
}
__device__ __forceinline__ uint32_t pack_bf16x2(float lo, float hi) {
    uint32_t r;
    asm("cvt.rn.bf16x2.f32 %0, %1, %2;" : "=r"(r) : "f"(hi), "f"(lo));
    return r;
}
__device__ __forceinline__ void mma_bf16(float* c, const uint32_t* a, uint32_t b0, uint32_t b1) {
    asm volatile(
        "mma.sync.aligned.m16n8k16.row.col.f32.bf16.bf16.f32 "
        "{%0,%1,%2,%3},{%4,%5,%6,%7},{%8,%9},{%0,%1,%2,%3};"
        : "+f"(c[0]), "+f"(c[1]), "+f"(c[2]), "+f"(c[3])
        : "r"(a[0]), "r"(a[1]), "r"(a[2]), "r"(a[3]), "r"(b0), "r"(b1));
}

#define MBARRIER_INIT(mbar, count) \
    asm volatile("mbarrier.init.shared.b64 [%0], %1;" :: "r"((uint32_t)(mbar)), "r"((uint32_t)(count)) : "memory")
#define MBARRIER_EXPECT_TX(mbar, tx) \
    asm volatile("mbarrier.arrive.expect_tx.shared.b64 _, [%0], %1;" :: "r"((uint32_t)(mbar)), "r"((uint32_t)(tx)) : "memory")
#define MBARRIER_WAIT_PARITY(mbar_smem_addr, phase_parity) do { \
    uint32_t _mbar = (uint32_t)(mbar_smem_addr); \
    uint32_t _parity = (uint32_t)(phase_parity); \
    uint32_t _done; \
    asm volatile( \
        "{\n\t.reg .pred p;\n\t" \
        "mbarrier.try_wait.parity.acquire.cta.shared::cta.b64 p, [%1], %2;\n\t" \
        "selp.b32 %0, 1, 0, p;\n\t}" \
        : "=r"(_done) : "r"(_mbar), "r"(_parity) : "memory"); \
    if (!_done) { \
        asm volatile( \
            "{\n\t.reg .pred P1;\n\t" \
            "WAIT_LOOP_%=:\n\t" \
            "mbarrier.try_wait.parity.acquire.cta.shared::cta.b64 P1, [%0], %1, 0x989680;\n\t" \
            "@P1 bra.uni WAIT_DONE_%=;\n\t" \
            "bra.uni WAIT_LOOP_%=;\n\t" \
            "WAIT_DONE_%=:\n\t}" \
            :: "r"(_mbar), "r"(_parity) : "memory"); \
    } \
} while(0)

// byte offset of element (kg, n) inside g_yaugB (fragment-register layout)
__device__ __forceinline__ uint32_t b_offset(int kg, int n) {
    int gc  = kg >> 5;
    int k16 = (kg >> 4) & 1;
    int kl  = kg & 15;
    int nt  = n >> 3;
    int n8  = n & 7;
    int lane = n8 * 4 + ((kl & 7) >> 1);
    return (uint32_t)(((gc * 2 + k16) * NTILES + nt) * 256 + lane * 8
                      + ((kl >> 3) & 1) * 4 + (kl & 1) * 2);
}

// ---------------- prep: sq + fragment-packed bf16 Yaug ----------------
__global__ void prep(const float* __restrict__ Y) {
    int w    = (blockIdx.x * blockDim.x + threadIdx.x) >> 5;
    int lane = threadIdx.x & 31;
    if (w >= NROW) return;
    if (w == 0 && lane == 0) g_cnt = 0;

    const float* yr = Y + (size_t)w * KDIM;
    float v0 = yr[lane], v1 = yr[lane + 32];
    float s = v0 * v0 + v1 * v1;
#pragma unroll
    for (int o = 16; o; o >>= 1) s += __shfl_xor_sync(0xffffffffu, s, o);
    if (lane == 0) g_sq[w] = s;

    *reinterpret_cast<__nv_bfloat16*>(g_yaugB + b_offset(w, lane))      = __float2bfloat16_rn(v0);
    *reinterpret_cast<__nv_bfloat16*>(g_yaugB + b_offset(w, lane + 32)) = __float2bfloat16_rn(v1);
    if (lane < 8) {
        float v = (lane == 0) ? 1.0f : (lane == 1) ? s : 0.0f;
        *reinterpret_cast<__nv_bfloat16*>(g_yaugB + b_offset(w, 64 + lane)) = __float2bfloat16_rn(v);
    }
}

// ---------------- main: TMA ring, TILE_M=256, 32 rows/warp (halved B-LDS) ----------------
__global__ __launch_bounds__(NTHREADS, 2)
void spectral_main(const __grid_constant__ CUtensorMap tmapA,
                   const float* __restrict__ Y, float* __restrict__ out) {
    extern __shared__ char smem_raw[];
    char* base = reinterpret_cast<char*>(
        (reinterpret_cast<uintptr_t>(smem_raw) + 1023) & ~(uintptr_t)1023);
    const uint32_t sb = smem_to_u32(base);       // A stages at 0,32K,64K (1024-aligned)
    char* bbase = base + 3 * A_STAGE;            // B stages at +0,+4608,+9216

    __shared__ __align__(8) uint64_t mbar_store[3];
    __shared__ float red[8];
    __shared__ int flag;
    const uint32_t mb0 = smem_to_u32(mbar_store);

    const int tid  = threadIdx.x;
    const int wid  = tid >> 5;       // 0..7 -> rows wid*32..wid*32+31
    const int lane = tid & 31;
    const int g    = lane >> 2;
    const int tg   = lane & 3;
    const int m0   = blockIdx.x * TILE_M;

    // uneven k-split: by<4 -> 29 chunks, else 28
    const int by    = blockIdx.y;
    const int count = 28 + (by < 4 ? 1 : 0);
    const int cs    = 28 * by + ((by < 4) ? by : 4);
    const int kbase = cs * KC;

    float acc[2][NTILES][4];
#pragma unroll
    for (int mf = 0; mf < 2; ++mf)
#pragma unroll
        for (int nt = 0; nt < NTILES; ++nt)
#pragma unroll
            for (int q = 0; q < 4; ++q) acc[mf][nt][q] = 0.0f;

    if (tid == 0) {
#pragma unroll
        for (int s = 0; s < 3; ++s) MBARRIER_INIT(mb0 + s * 8, 1);
    }
    __syncthreads();

    // single-thread issue: one 2D TMA (A, SW128, 256x128B) + one 1D bulk (B)
    auto issue = [&](int t, int s) {
        const uint32_t mb   = mb0 + (uint32_t)s * 8;
        const uint32_t adst = sb + (uint32_t)s * A_STAGE;
        const uint32_t bdst = smem_to_u32(bbase) + (uint32_t)s * BCH_BYTES;
        const int k0 = kbase + t * KC;
        MBARRIER_EXPECT_TX(mb, CHUNK_TX);
        asm volatile(
            "cp.async.bulk.tensor.2d.shared::cta.global.tile.mbarrier::complete_tx::bytes "
            "[%0], [%1, {%2, %3}], [%4];"
            :: "r"(adst), "l"(&tmapA), "r"(k0), "r"(m0), "r"(mb) : "memory");
        const unsigned char* bsrc = g_yaugB + (size_t)(k0 >> 5) * BCH_BYTES;
        asm volatile(
            "cp.async.bulk.shared::cluster.global.mbarrier::complete_tx::bytes "
            "[%0], [%1], %2, [%3];"
            :: "r"(bdst), "l"(bsrc), "r"((uint32_t)BCH_BYTES), "r"(mb) : "memory");
    };

    if (tid == 0) { issue(0, 0); issue(1, 1); issue(2, 2); }

    int s = 0, ph = 0;
    const int gx = g << 4;           // SW128: linear_off ^ ((row&7)<<4); row&7 == g here
    for (int t = 0; t < count; ++t) {
        MBARRIER_WAIT_PARITY(mb0 + s * 8, ph);

        const char* abp = base + (size_t)s * A_STAGE;
        const char* bbp = bbase + (size_t)s * BCH_BYTES;

#pragma unroll
        for (int ks = 0; ks < 2; ++ks) {
            uint32_t a[2][4];
#pragma unroll
            for (int mf = 0; mf < 2; ++mf) {
                const int row = wid * 32 + mf * 16 + g;
                const int off0 = row * 128 + ks * 64 + tg * 8;
                float2 v0 = *reinterpret_cast<const float2*>(abp + ((off0)        ^ gx));
                float2 v1 = *reinterpret_cast<const float2*>(abp + ((off0 + 1024) ^ gx));
                float2 v2 = *reinterpret_cast<const float2*>(abp + ((off0 + 32)   ^ gx));
                float2 v3 = *reinterpret_cast<const float2*>(abp + ((off0 + 1056) ^ gx));
                a[mf][0] = pack_bf16x2(v0.x, v0.y);
                a[mf][1] = pack_bf16x2(v1.x, v1.y);
                a[mf][2] = pack_bf16x2(v2.x, v2.y);
                a[mf][3] = pack_bf16x2(v3.x, v3.y);
            }
#pragma unroll
            for (int nt = 0; nt < NTILES; ++nt) {
                uint2 b = *reinterpret_cast<const uint2*>(
                    bbp + (ks * NTILES + nt) * 256 + lane * 8);
                mma_bf16(acc[0][nt], a[0], b.x, b.y);
                mma_bf16(acc[1][nt], a[1], b.x, b.y);
            }
        }

        __syncthreads();                       // all threads done reading stage s
        if (t + 3 < count && tid == 0) issue(t + 3, s);
        if (++s == 3) { s = 0; ph ^= 1; }
    }

    // ---- epilogue: contract Z fragments against coefficients ----
    float partial = 0.0f;
#pragma unroll
    for (int mf = 0; mf < 2; ++mf) {
#pragma unroll
        for (int half = 0; half < 2; ++half) {
            int i = m0 + wid * 32 + mf * 16 + half * 8 + g;
            const float* yr = Y + (size_t)i * KDIM;
            float sacc = 0.0f;
#pragma unroll
            for (int nt = 0; nt < 8; ++nt) {
                int col = nt * 8 + tg * 2;
                sacc = fmaf(yr[col],     acc[mf][nt][half * 2 + 0], sacc);
                sacc = fmaf(yr[col + 1], acc[mf][nt][half * 2 + 1], sacc);
            }
            float e = -2.0f * sacc;
            if (tg == 0) {
                e = fmaf(g_sq[i], acc[mf][8][half * 2 + 0], e);
                e += acc[mf][8][half * 2 + 1];
            }
            partial += e;
        }
    }
#pragma unroll
    for (int o = 16; o; o >>= 1) partial += __shfl_xor_sync(0xffffffffu, partial, o);

    if (lane == 0) red[wid] = partial;
    __syncthreads();

    // ---- last-block deterministic final reduction (288 partials) ----
    if (tid == 0) {
        float c = 0.0f;
#pragma unroll
        for (int j = 0; j < 8; ++j) c += red[j];
        g_part[blockIdx.y * MTILES + blockIdx.x] = c;
        __threadfence();
        unsigned int old = atomicAdd(&g_cnt, 1u);
        flag = (old == NPART - 1) ? 1 : 0;
    }
    __syncthreads();
    if (flag) {
        __threadfence();
        float sv = g_part[tid] + ((tid < NPART - 256) ? g_part[tid + 256] : 0.0f);
#pragma unroll
        for (int o = 16; o; o >>= 1) sv += __shfl_xor_sync(0xffffffffu, sv, o);
        if (lane == 0) red[wid] = sv;
        __syncthreads();
        if (tid == 0) {
            float tot = 0.0f;
#pragma unroll
            for (int j = 0; j < 8; ++j) tot += red[j];
            out[0] = tot * (1.0f / (2.0f * (float)NROW));
            g_cnt = 0;
        }
    }
}

// ---------------- launch ----------------
typedef CUresult (CUDAAPI *tmap_encode_fn)(
    CUtensorMap*, CUtensorMapDataType, cuuint32_t, void*,
    const cuuint64_t*, const cuuint64_t*, const cuuint32_t*, const cuuint32_t*,
    CUtensorMapInterleave, CUtensorMapSwizzle, CUtensorMapL2promotion,
    CUtensorMapFloatOOBfill);

extern "C" void kernel_launch(void* const* d_in, const int* in_sizes, int n_in,
                              void* d_out, int out_size) {
    const float* W;
    const float* Y;
    if (in_sizes[0] == NROW * NROW) {
        W = (const float*)d_in[0];
        Y = (const float*)d_in[1];
    } else {
        Y = (const float*)d_in[0];
        W = (const float*)d_in[1];
    }

    tmap_encode_fn enc = nullptr;
    cudaDriverEntryPointQueryResult qres;
    cudaGetDriverEntryPointByVersion("cuTensorMapEncodeTiled", (void**)&enc,
                                     12000, cudaEnableDefault, &qres);
    CUtensorMap tmapA;
    {
        cuuint64_t dims[2]    = {NROW, NROW};          // x (contiguous), y
        cuuint64_t strides[1] = {(cuuint64_t)NROW * 4};
        cuuint32_t box[2]     = {32, TILE_M};          // 32 fp32 = 128B x 256 rows
        cuuint32_t es[2]      = {1, 1};
        enc(&tmapA, CU_TENSOR_MAP_DATA_TYPE_FLOAT32, 2, (void*)W,
            dims, strides, box, es,
            CU_TENSOR_MAP_INTERLEAVE_NONE, CU_TENSOR_MAP_SWIZZLE_128B,
            CU_TENSOR_MAP_L2_PROMOTION_L2_128B, CU_TENSOR_MAP_FLOAT_OOB_FILL_NONE);
    }

    cudaFuncSetAttribute(spectral_main, cudaFuncAttributeMaxDynamicSharedMemorySize, DYN_BYTES);

    prep<<<NROW / 8, 256>>>(Y);
    spectral_main<<<dim3(MTILES, NSPLIT), NTHREADS, DYN_BYTES>>>(tmapA, Y, (float*)d_out);
}